// round 12
// baseline (speedup 1.0000x reference)
#include <cuda_runtime.h>
#include <cuda_fp16.h>
#include <stdint.h>
#include <math.h>

// out[i] = F(x[i]) for a fixed smooth scalar F (weights shared across elems).
// SINGLE fused kernel:
//   blocks 0..127: L2-prefetch their x slice, then exact warp-per-entry
//                  tabulation of F (1024 nodes, half2 pairs), arrive on counter.
//   others:        front-batch x loads (overlaps the build), spin-wait,
//                  stage dual-copy 8KB table to smem, linear interpolation.
// One-pass (sum, sumsq) LayerNorm reductions shorten the build critical path.

#define HH 20
#define GG 80
#define LN_EPS 1e-5f

#define TAB_N 1024
#define TAB_XMIN (-6.5f)
#define TAB_XMAX (6.5f)
#define TAB_STEP ((TAB_XMAX - TAB_XMIN) / (float)(TAB_N - 1))
#define TAB_INV_STEP ((float)(TAB_N - 1) / (TAB_XMAX - TAB_XMIN))
#define TAB_T_OFF (-(TAB_XMIN) * TAB_INV_STEP)
#define TAB_T_MAX ((float)(TAB_N - 1) - 0.001f)
// normalized form for __saturatef clamp: t = saturate(x*A + B) * TAB_T_MAX
#define TAB_A (TAB_INV_STEP / TAB_T_MAX)
#define TAB_B (TAB_T_OFF / TAB_T_MAX)

#define NBUILD 128       // builder blocks (8 entries each)
#define VPT 4            // k-strided float4 batches per thread
#define IBLOCKS 1184     // 8 CTAs/SM x 148 SMs

__device__ __half2 g_tab_h2[TAB_N];   // {F[j], F[j+1]}
__device__ volatile int g_count;      // build-arrival counter
__device__ int g_exit;                // exit counter for the reset

struct Weights {
    const float *W1, *b1, *g1, *be1;
    const float *Wih0, *gi0, *bi0, *bh0, *go0, *bo0;
    const float *Wih1, *gi1, *bi1, *bh1, *go1, *bo1;
    const float *Wout, *bout;
};

__device__ __forceinline__ float fast_sigmoid(float z) {
    return 1.0f / (1.0f + __expf(-z));
}
__device__ __forceinline__ float fast_tanh(float z) {
    return 1.0f - 2.0f / (1.0f + __expf(2.0f * z));
}
__device__ __forceinline__ float warp_sum(float v) {
#pragma unroll
    for (int off = 16; off; off >>= 1) v += __shfl_xor_sync(0xffffffffu, v, off);
    return v;
}
// interleaved two-value reduction: the two shfl chains pipeline
__device__ __forceinline__ float2 warp_sum2(float a, float b) {
#pragma unroll
    for (int off = 16; off; off >>= 1) {
        a += __shfl_xor_sync(0xffffffffu, a, off);
        b += __shfl_xor_sync(0xffffffffu, b, off);
    }
    return make_float2(a, b);
}

// ---------------- build helpers (warp-collective LN-LSTM cell) --------------
#define WPITCH 21
#define WROWS  96

__device__ __forceinline__ float cell_warp(const float* __restrict__ v,
                                           const float* __restrict__ Wsm,
                                           const float* gi, const float* bi,
                                           const float* bh, const float* go,
                                           const float* bo, float* gbuf,
                                           int lane) {
    const bool act = lane < HH;
    const float* w0 = Wsm + lane * WPITCH;
    const float* w1 = Wsm + (32 + lane) * WPITCH;
    const float* w2 = Wsm + (64 + lane) * WPITCH;  // rows >= 80 are zero
    float a0 = 0.f, a1 = 0.f, a2 = 0.f;
#pragma unroll
    for (int k = 0; k < HH; k++) {
        a0 = fmaf(v[k], w0[k], a0);
        a1 = fmaf(v[k], w1[k], a1);
        a2 = fmaf(v[k], w2[k], a2);   // lanes >= 16: zero rows -> a2 == 0
    }
    // one-pass moments over the 80 gate values
    float s1l = a0 + a1 + a2;
    float s2l = fmaf(a0, a0, fmaf(a1, a1, a2 * a2));
    float2 s = warp_sum2(s1l, s2l);
    float mu = s.x * (1.f / 80.f);
    float var = fmaxf((s.y - s.x * mu) * (1.f / 79.f), 0.f);
    float inv = 1.f / (sqrtf(var) + LN_EPS);
    gbuf[lane]      = (a0 - mu) * inv * gi[lane]      + bi[lane]      + bh[lane];
    gbuf[32 + lane] = (a1 - mu) * inv * gi[32 + lane] + bi[32 + lane] + bh[32 + lane];
    if (lane < 16)
        gbuf[64 + lane] = (a2 - mu) * inv * gi[64 + lane] + bi[64 + lane] + bh[64 + lane];
    __syncwarp();
    float c = 0.f, ov = 0.f;
    if (act) {
        float iv = gbuf[lane];
        ov = gbuf[40 + lane];
        float gv = gbuf[60 + lane];
        c = fast_sigmoid(iv) * fast_tanh(gv);
    }
    __syncwarp();
    // one-pass moments over the 20 cell values (c==0 for inactive lanes)
    float2 s2 = warp_sum2(c, c * c);
    float mu2 = s2.x * (1.f / 20.f);
    float var2 = fmaxf((s2.y - s2.x * mu2) * (1.f / 19.f), 0.f);
    float inv2 = 1.f / (sqrtf(var2) + LN_EPS);
    float h = 0.f;
    if (act) {
        float cn = (c - mu2) * inv2 * go[lane] + bo[lane];
        h = fast_sigmoid(ov) * fast_tanh(cn);
    }
    return h;
}

// ---------------- interpolation (dual-copy half2 table in smem) -------------
__device__ __forceinline__ float interp_one_s(float xx, int par,
                                              const unsigned int* __restrict__ tab) {
    float t = __saturatef(fmaf(xx, TAB_A, TAB_B)) * TAB_T_MAX;
    int i = __float2int_rd(t);
    float s = t - (float)i;
    unsigned int u = tab[(i << 1) | par];         // lane-parity copy
    __half2 h = *reinterpret_cast<const __half2*>(&u);
    float2 q = __half22float2(h);                 // {F[i], F[i+1]}
    return fmaf(s, q.y - q.x, q.x);
}

// ---------------- the fused kernel ------------------------------------------
__global__ void __launch_bounds__(256)
fused_kernel(Weights w, const float4* __restrict__ x4, float4* __restrict__ o4,
             int n4, const float* __restrict__ x, float* __restrict__ out,
             int n) {
    __shared__ union SmemU {
        struct {
            float Wih0_s[WROWS * WPITCH];
            float Wih1_s[WROWS * WPITCH];
            float gates[8][GG];
            float hx[8][HH];
        } b;
        unsigned int tab[2 * TAB_N];   // dual copy, 8KB
    } smem;

    int tid = threadIdx.x, warp = tid >> 5, lane = tid & 31;
    int gtid = blockIdx.x * 256 + tid;
    int stride = gridDim.x * 256;
    const bool builder = blockIdx.x < NBUILD;

    float4 xv[VPT];
    bool vld[VPT];

    if (builder) {
        // L2-prefetch this block's x slice (no registers held through build)
#pragma unroll
        for (int k = 0; k < VPT; k++) {
            int idx = gtid + k * stride;
            if (idx < n4)
                asm volatile("prefetch.global.L2 [%0];" :: "l"(x4 + idx));
        }

        // ---- build 8 table entries (one per warp) ----
        for (int idx = tid; idx < WROWS * WPITCH; idx += 256) {
            int r = idx / WPITCH, k = idx - r * WPITCH;
            float v0 = 0.f, v1 = 0.f;
            if (r < GG && k < HH) {
                v0 = w.Wih0[r * HH + k];
                v1 = w.Wih1[r * HH + k];
            }
            smem.b.Wih0_s[idx] = v0;
            smem.b.Wih1_s[idx] = v1;
        }
        __syncthreads();

        int entry = blockIdx.x * 8 + warp;
        float xe = fmaf((float)entry, TAB_STEP, TAB_XMIN);
        const bool act = lane < HH;

        // layer 1 (one-pass moments; hval==0 for inactive lanes)
        float hval = 0.f;
        if (act) hval = fmaf(xe, w.W1[lane], w.b1[lane]);
        {
            float2 s = warp_sum2(hval, hval * hval);
            float mu = s.x * (1.f / 20.f);
            float var = fmaxf((s.y - s.x * mu) * (1.f / 19.f), 0.f);
            float inv = 1.f / (sqrtf(var) + LN_EPS);
            if (act) hval = fast_tanh((hval - mu) * inv * w.g1[lane] + w.be1[lane]);
        }

        float v[HH];
        if (act) smem.b.hx[warp][lane] = hval;
        __syncwarp();
#pragma unroll
        for (int k = 0; k < HH; k++) v[k] = smem.b.hx[warp][k];
        __syncwarp();

        hval = cell_warp(v, smem.b.Wih0_s, w.gi0, w.bi0, w.bh0, w.go0, w.bo0,
                         smem.b.gates[warp], lane);

        if (act) smem.b.hx[warp][lane] = hval;
        __syncwarp();
#pragma unroll
        for (int k = 0; k < HH; k++) v[k] = smem.b.hx[warp][k];
        __syncwarp();

        hval = cell_warp(v, smem.b.Wih1_s, w.gi1, w.bi1, w.bh1, w.go1, w.bo1,
                         smem.b.gates[warp], lane);

        float p = act ? hval * w.Wout[lane] : 0.f;
        p = warp_sum(p);
        if (lane == 0) {
            float val = p + w.bout[0];
            __half hv = __float2half_rn(val);
            __half* H = reinterpret_cast<__half*>(g_tab_h2);
            H[2 * entry] = hv;                       // pair[entry].x
            if (entry > 0) H[2 * entry - 1] = hv;    // pair[entry-1].y
            if (entry == TAB_N - 1) H[2 * entry + 1] = hv;  // defined
        }
        __syncthreads();
        if (tid == 0) {
            __threadfence();
            atomicAdd((int*)&g_count, 1);
        }
    } else {
        // ---- front-batch x loads: DRAM/L2 fetch overlaps the build ----
#pragma unroll
        for (int k = 0; k < VPT; k++) {
            int idx = gtid + k * stride;
            vld[k] = idx < n4;
            if (vld[k]) xv[k] = __ldcs(&x4[idx]);
        }
    }

    // ---- grid barrier: wait for the table ----
    if (tid == 0) {
        while (g_count < NBUILD) { __nanosleep(64); }
        __threadfence();
    }
    __syncthreads();

    // ---- stage dual-copy table (8KB): each of 256 threads expands one uint4
    {
        uint4 tu = __ldcg(((const uint4*)g_tab_h2) + tid);
        unsigned int* t = smem.tab + 8 * tid;
        t[0] = tu.x; t[1] = tu.x;
        t[2] = tu.y; t[3] = tu.y;
        t[4] = tu.z; t[5] = tu.z;
        t[6] = tu.w; t[7] = tu.w;
    }
    __syncthreads();

    if (builder) {   // builders load their (L2-prefetched) x batch now
#pragma unroll
        for (int k = 0; k < VPT; k++) {
            int idx = gtid + k * stride;
            vld[k] = idx < n4;
            if (vld[k]) xv[k] = __ldcs(&x4[idx]);
        }
    }

    const int par = lane & 1;

    // ---- interpolate + stream out ----
#pragma unroll
    for (int k = 0; k < VPT; k++) {
        if (!vld[k]) continue;
        float4 ov;
        ov.x = interp_one_s(xv[k].x, par, smem.tab);
        ov.y = interp_one_s(xv[k].y, par, smem.tab);
        ov.z = interp_one_s(xv[k].z, par, smem.tab);
        ov.w = interp_one_s(xv[k].w, par, smem.tab);
        __stcs(&o4[gtid + k * stride], ov);
    }

    // n % 4 tail
    if (blockIdx.x == 0 && tid < 32) {
        for (int i = n4 * 4 + tid; i < n; i += 32)
            out[i] = interp_one_s(x[i], par, smem.tab);
    }

    // ---- exit: last block resets the barrier counters for the next replay --
    if (tid == 0) {
        int old = atomicAdd(&g_exit, 1);
        if (old == (int)gridDim.x - 1) {
            atomicExch((int*)&g_count, 0);
            atomicExch(&g_exit, 0);
        }
    }
}

extern "C" void kernel_launch(void* const* d_in, const int* in_sizes, int n_in,
                              void* d_out, int out_size) {
    Weights w;
    w.W1 = (const float*)d_in[1];
    w.b1 = (const float*)d_in[2];
    w.g1 = (const float*)d_in[3];
    w.be1 = (const float*)d_in[4];
    w.Wih0 = (const float*)d_in[5];
    w.gi0 = (const float*)d_in[7];
    w.bi0 = (const float*)d_in[8];
    w.bh0 = (const float*)d_in[10];
    w.go0 = (const float*)d_in[11];
    w.bo0 = (const float*)d_in[12];
    w.Wih1 = (const float*)d_in[13];
    w.gi1 = (const float*)d_in[15];
    w.bi1 = (const float*)d_in[16];
    w.bh1 = (const float*)d_in[18];
    w.go1 = (const float*)d_in[19];
    w.bo1 = (const float*)d_in[20];
    w.Wout = (const float*)d_in[21];
    w.bout = (const float*)d_in[22];

    const float* x = (const float*)d_in[0];
    float* out = (float*)d_out;
    int n = in_sizes[0];
    int n4 = n / 4;

    int blocks = IBLOCKS;
    if ((long long)blocks * 256 * VPT < (long long)n4)
        blocks = (int)(((long long)n4 + 256LL * VPT - 1) / (256LL * VPT));
    if (blocks < NBUILD) blocks = NBUILD;

    fused_kernel<<<blocks, 256>>>(w, (const float4*)x, (float4*)out, n4,
                                  x, out, n);
}

// round 13
// speedup vs baseline: 1.0017x; 1.0017x over previous
#include <cuda_runtime.h>
#include <cuda_fp16.h>
#include <stdint.h>
#include <math.h>

// out[i] = F(x[i]) for a fixed smooth scalar F (weights shared across elems).
// SINGLE fused kernel (R11 baseline + default-cached x loads):
//   blocks 0..127: exact warp-per-entry tabulation of F (1024 nodes, half2
//                  pairs {F[j],F[j+1]}), then arrive on a device counter.
//   all blocks:    front-batch x loads (non-builders, overlaps the build),
//                  spin-wait for the table, stage 4KB into smem, then
//                  streaming linear interpolation (one LDS.32 per element).
// x loads use DEFAULT caching (not .cs): across CUDA-graph replays the 16MB
// input stays L2-resident, turning DRAM refetches into L2 hits.

#define HH 20
#define GG 80
#define LN_EPS 1e-5f

#define TAB_N 1024
#define TAB_XMIN (-6.5f)
#define TAB_XMAX (6.5f)
#define TAB_STEP ((TAB_XMAX - TAB_XMIN) / (float)(TAB_N - 1))
#define TAB_INV_STEP ((float)(TAB_N - 1) / (TAB_XMAX - TAB_XMIN))
#define TAB_T_OFF (-(TAB_XMIN) * TAB_INV_STEP)
#define TAB_T_MAX ((float)(TAB_N - 1) - 0.001f)

#define NBUILD 128       // builder blocks (8 entries each)
#define VPT 4            // k-strided float4 batches per thread
#define IBLOCKS 1184     // 8 CTAs/SM x 148 SMs

__device__ __half2 g_tab_h2[TAB_N];   // {F[j], F[j+1]}
__device__ volatile int g_count;      // build-arrival counter (reset each run)
__device__ int g_exit;                // exit counter for the reset

struct Weights {
    const float *W1, *b1, *g1, *be1;
    const float *Wih0, *gi0, *bi0, *bh0, *go0, *bo0;
    const float *Wih1, *gi1, *bi1, *bh1, *go1, *bo1;
    const float *Wout, *bout;
};

__device__ __forceinline__ float fast_sigmoid(float z) {
    return 1.0f / (1.0f + __expf(-z));
}
__device__ __forceinline__ float fast_tanh(float z) {
    return 1.0f - 2.0f / (1.0f + __expf(2.0f * z));
}
__device__ __forceinline__ float warp_sum(float v) {
#pragma unroll
    for (int off = 16; off; off >>= 1) v += __shfl_xor_sync(0xffffffffu, v, off);
    return v;
}

// ---------------- build helpers (warp-collective LN-LSTM cell) --------------
#define WPITCH 21
#define WROWS  96

__device__ __forceinline__ float cell_warp(const float* __restrict__ v,
                                           const float* __restrict__ Wsm,
                                           const float* gi, const float* bi,
                                           const float* bh, const float* go,
                                           const float* bo, float* gbuf,
                                           int lane) {
    const bool v2 = lane < 16;
    const bool act = lane < HH;
    const float* w0 = Wsm + lane * WPITCH;
    const float* w1 = Wsm + (32 + lane) * WPITCH;
    const float* w2 = Wsm + (64 + lane) * WPITCH;  // rows >= 80 are zero
    float a0 = 0.f, a1 = 0.f, a2 = 0.f;
#pragma unroll
    for (int k = 0; k < HH; k++) {
        a0 = fmaf(v[k], w0[k], a0);
        a1 = fmaf(v[k], w1[k], a1);
        a2 = fmaf(v[k], w2[k], a2);
    }
    float mu = warp_sum(a0 + a1 + a2) * (1.f / 80.f);
    float d0 = a0 - mu, d1 = a1 - mu, d2 = v2 ? (a2 - mu) : 0.f;
    float var = warp_sum(fmaf(d0, d0, fmaf(d1, d1, d2 * d2))) * (1.f / 79.f);
    float inv = 1.f / (sqrtf(var) + LN_EPS);
    gbuf[lane]      = d0 * inv * gi[lane]      + bi[lane]      + bh[lane];
    gbuf[32 + lane] = d1 * inv * gi[32 + lane] + bi[32 + lane] + bh[32 + lane];
    if (v2)
        gbuf[64 + lane] = d2 * inv * gi[64 + lane] + bi[64 + lane] + bh[64 + lane];
    __syncwarp();
    float c = 0.f, ov = 0.f;
    if (act) {
        float iv = gbuf[lane];
        ov = gbuf[40 + lane];
        float gv = gbuf[60 + lane];
        c = fast_sigmoid(iv) * fast_tanh(gv);
    }
    __syncwarp();
    float mu2 = warp_sum(c) * (1.f / 20.f);
    float dc = act ? (c - mu2) : 0.f;
    float var2 = warp_sum(dc * dc) * (1.f / 19.f);
    float inv2 = 1.f / (sqrtf(var2) + LN_EPS);
    float h = 0.f;
    if (act) {
        float cn = dc * inv2 * go[lane] + bo[lane];
        h = fast_sigmoid(ov) * fast_tanh(cn);
    }
    return h;
}

// ---------------- interpolation (half2 table in smem) -----------------------
__device__ __forceinline__ float interp_one_s(float xx,
                                              const unsigned int* __restrict__ tab) {
    float t = fmaf(xx, TAB_INV_STEP, TAB_T_OFF);
    t = fminf(fmaxf(t, 0.0f), TAB_T_MAX);        // clamp in t-space
    int i = __float2int_rd(t);
    float s = t - (float)i;
    unsigned int u = tab[i];                      // one LDS.32 (random banks)
    __half2 h = *reinterpret_cast<const __half2*>(&u);
    float2 q = __half22float2(h);                 // {F[i], F[i+1]}
    return fmaf(s, q.y - q.x, q.x);
}

// ---------------- the fused kernel ------------------------------------------
__global__ void __launch_bounds__(256)
fused_kernel(Weights w, const float4* __restrict__ x4, float4* __restrict__ o4,
             int n4, const float* __restrict__ x, float* __restrict__ out,
             int n) {
    __shared__ union SmemU {
        struct {
            float Wih0_s[WROWS * WPITCH];
            float Wih1_s[WROWS * WPITCH];
            float gates[8][GG];
            float hx[8][HH];
        } b;
        unsigned int tab[TAB_N];
    } smem;

    int tid = threadIdx.x, warp = tid >> 5, lane = tid & 31;
    int gtid = blockIdx.x * 256 + tid;
    int stride = gridDim.x * 256;
    const bool builder = blockIdx.x < NBUILD;

    float4 xv[VPT];
    bool vld[VPT];

    if (builder) {
        // ---- build 8 table entries (one per warp) ----
        for (int idx = tid; idx < WROWS * WPITCH; idx += 256) {
            int r = idx / WPITCH, k = idx - r * WPITCH;
            float v0 = 0.f, v1 = 0.f;
            if (r < GG && k < HH) {
                v0 = w.Wih0[r * HH + k];
                v1 = w.Wih1[r * HH + k];
            }
            smem.b.Wih0_s[idx] = v0;
            smem.b.Wih1_s[idx] = v1;
        }
        __syncthreads();

        int entry = blockIdx.x * 8 + warp;
        float xe = fmaf((float)entry, TAB_STEP, TAB_XMIN);
        const bool act = lane < HH;

        // layer 1
        float hval = 0.f;
        if (act) hval = fmaf(xe, w.W1[lane], w.b1[lane]);
        {
            float mu = warp_sum(act ? hval : 0.f) * (1.f / 20.f);
            float d = act ? (hval - mu) : 0.f;
            float var = warp_sum(d * d) * (1.f / 19.f);
            float inv = 1.f / (sqrtf(var) + LN_EPS);
            if (act) hval = fast_tanh(d * inv * w.g1[lane] + w.be1[lane]);
        }

        float v[HH];
        if (act) smem.b.hx[warp][lane] = hval;
        __syncwarp();
#pragma unroll
        for (int k = 0; k < HH; k++) v[k] = smem.b.hx[warp][k];
        __syncwarp();

        hval = cell_warp(v, smem.b.Wih0_s, w.gi0, w.bi0, w.bh0, w.go0, w.bo0,
                         smem.b.gates[warp], lane);

        if (act) smem.b.hx[warp][lane] = hval;
        __syncwarp();
#pragma unroll
        for (int k = 0; k < HH; k++) v[k] = smem.b.hx[warp][k];
        __syncwarp();

        hval = cell_warp(v, smem.b.Wih1_s, w.gi1, w.bi1, w.bh1, w.go1, w.bo1,
                         smem.b.gates[warp], lane);

        float p = act ? hval * w.Wout[lane] : 0.f;
        p = warp_sum(p);
        if (lane == 0) {
            float val = p + w.bout[0];
            __half hv = __float2half_rn(val);
            __half* H = reinterpret_cast<__half*>(g_tab_h2);
            H[2 * entry] = hv;                       // pair[entry].x
            if (entry > 0) H[2 * entry - 1] = hv;    // pair[entry-1].y
            if (entry == TAB_N - 1) H[2 * entry + 1] = hv;  // defined
        }
        __syncthreads();
        if (tid == 0) {
            __threadfence();
            atomicAdd((int*)&g_count, 1);
        }
    } else {
        // ---- front-batch x loads (DEFAULT cache: L2-warm across replays) ---
#pragma unroll
        for (int k = 0; k < VPT; k++) {
            int idx = gtid + k * stride;
            vld[k] = idx < n4;
            if (vld[k]) xv[k] = x4[idx];
        }
    }

    // ---- grid barrier: wait for the table ----
    if (tid == 0) {
        while (g_count < NBUILD) { }
        __threadfence();
    }
    __syncthreads();

    // ---- stage 4KB half2 table into smem (one uint4 per thread) ----
    ((uint4*)smem.tab)[tid] = __ldcg(((const uint4*)g_tab_h2) + tid);
    __syncthreads();

    if (builder) {   // builders load their x batch now (L2-warm)
#pragma unroll
        for (int k = 0; k < VPT; k++) {
            int idx = gtid + k * stride;
            vld[k] = idx < n4;
            if (vld[k]) xv[k] = x4[idx];
        }
    }

    // ---- interpolate + stream out ----
#pragma unroll
    for (int k = 0; k < VPT; k++) {
        if (!vld[k]) continue;
        float4 ov;
        ov.x = interp_one_s(xv[k].x, smem.tab);
        ov.y = interp_one_s(xv[k].y, smem.tab);
        ov.z = interp_one_s(xv[k].z, smem.tab);
        ov.w = interp_one_s(xv[k].w, smem.tab);
        __stcs(&o4[gtid + k * stride], ov);
    }

    // n % 4 tail
    if (blockIdx.x == 0 && tid < 32) {
        for (int i = n4 * 4 + tid; i < n; i += 32)
            out[i] = interp_one_s(x[i], smem.tab);
    }

    // ---- exit: last block resets the barrier counters for the next replay --
    if (tid == 0) {
        int old = atomicAdd(&g_exit, 1);
        if (old == (int)gridDim.x - 1) {
            atomicExch((int*)&g_count, 0);
            atomicExch(&g_exit, 0);
        }
    }
}

extern "C" void kernel_launch(void* const* d_in, const int* in_sizes, int n_in,
                              void* d_out, int out_size) {
    Weights w;
    w.W1 = (const float*)d_in[1];
    w.b1 = (const float*)d_in[2];
    w.g1 = (const float*)d_in[3];
    w.be1 = (const float*)d_in[4];
    w.Wih0 = (const float*)d_in[5];
    w.gi0 = (const float*)d_in[7];
    w.bi0 = (const float*)d_in[8];
    w.bh0 = (const float*)d_in[10];
    w.go0 = (const float*)d_in[11];
    w.bo0 = (const float*)d_in[12];
    w.Wih1 = (const float*)d_in[13];
    w.gi1 = (const float*)d_in[15];
    w.bi1 = (const float*)d_in[16];
    w.bh1 = (const float*)d_in[18];
    w.go1 = (const float*)d_in[19];
    w.bo1 = (const float*)d_in[20];
    w.Wout = (const float*)d_in[21];
    w.bout = (const float*)d_in[22];

    const float* x = (const float*)d_in[0];
    float* out = (float*)d_out;
    int n = in_sizes[0];
    int n4 = n / 4;

    int blocks = IBLOCKS;
    if ((long long)blocks * 256 * VPT < (long long)n4)
        blocks = (int)(((long long)n4 + 256LL * VPT - 1) / (256LL * VPT));
    if (blocks < NBUILD) blocks = NBUILD;

    fused_kernel<<<blocks, 256>>>(w, (const float4*)x, (float4*)out, n4,
                                  x, out, n);
}

// round 14
// speedup vs baseline: 1.0991x; 1.0972x over previous
#include <cuda_runtime.h>
#include <cuda_fp16.h>
#include <stdint.h>
#include <math.h>

// out[i] = F(x[i]) for a fixed smooth scalar F (weights shared across elems).
// SINGLE fused kernel, v2:
//   blocks 0..127 : build the 1024-node half2 table (warp per entry) with an
//                   UNCONTENDED memory system, then arrive on a counter.
//   blocks >= 128 : sleep-poll the counter (nanosleep backoff — no L2 storm,
//                   no x-load flood competing with the build).
//   all blocks    : after release, stage the 4KB table to smem and run the
//                   blocked VPT=4 linear interpolation (R8's fastest shape).
// On timed graph replays x/out are L2-resident, so post-barrier x loads are
// L2 hits; pre-barrier prefetching is pointless and only slowed the build.

#define HH 20
#define GG 80
#define LN_EPS 1e-5f

#define TAB_N 1024
#define TAB_XMIN (-6.5f)
#define TAB_XMAX (6.5f)
#define TAB_STEP ((TAB_XMAX - TAB_XMIN) / (float)(TAB_N - 1))
#define TAB_INV_STEP ((float)(TAB_N - 1) / (TAB_XMAX - TAB_XMIN))
#define TAB_T_OFF (-(TAB_XMIN) * TAB_INV_STEP)
#define TAB_T_MAX ((float)(TAB_N - 1) - 0.001f)

#define NBUILD 128       // builder blocks, 8 entries each (8 warps)
#define VPT 4            // float4s per thread, blocked addressing

__device__ __half2 g_tab_h2[TAB_N];   // {F[j], F[j+1]}
__device__ volatile int g_count;      // build-arrival counter
__device__ int g_exit;                // exit counter for the reset

struct Weights {
    const float *W1, *b1, *g1, *be1;
    const float *Wih0, *gi0, *bi0, *bh0, *go0, *bo0;
    const float *Wih1, *gi1, *bi1, *bh1, *go1, *bo1;
    const float *Wout, *bout;
};

__device__ __forceinline__ float fast_sigmoid(float z) {
    return 1.0f / (1.0f + __expf(-z));
}
__device__ __forceinline__ float fast_tanh(float z) {
    return 1.0f - 2.0f / (1.0f + __expf(2.0f * z));
}
__device__ __forceinline__ float warp_sum(float v) {
#pragma unroll
    for (int off = 16; off; off >>= 1) v += __shfl_xor_sync(0xffffffffu, v, off);
    return v;
}

// ---------------- build helpers (warp-collective LN-LSTM cell) --------------
#define WPITCH 21
#define WROWS  96

__device__ __forceinline__ float cell_warp(const float* __restrict__ v,
                                           const float* __restrict__ Wsm,
                                           const float* gi, const float* bi,
                                           const float* bh, const float* go,
                                           const float* bo, float* gbuf,
                                           int lane) {
    const bool v2 = lane < 16;
    const bool act = lane < HH;
    const float* w0 = Wsm + lane * WPITCH;
    const float* w1 = Wsm + (32 + lane) * WPITCH;
    const float* w2 = Wsm + (64 + lane) * WPITCH;  // rows >= 80 are zero
    float a0 = 0.f, a1 = 0.f, a2 = 0.f;
#pragma unroll
    for (int k = 0; k < HH; k++) {
        a0 = fmaf(v[k], w0[k], a0);
        a1 = fmaf(v[k], w1[k], a1);
        a2 = fmaf(v[k], w2[k], a2);
    }
    float mu = warp_sum(a0 + a1 + a2) * (1.f / 80.f);
    float d0 = a0 - mu, d1 = a1 - mu, d2 = v2 ? (a2 - mu) : 0.f;
    float var = warp_sum(fmaf(d0, d0, fmaf(d1, d1, d2 * d2))) * (1.f / 79.f);
    float inv = 1.f / (sqrtf(var) + LN_EPS);
    gbuf[lane]      = d0 * inv * gi[lane]      + bi[lane]      + bh[lane];
    gbuf[32 + lane] = d1 * inv * gi[32 + lane] + bi[32 + lane] + bh[32 + lane];
    if (v2)
        gbuf[64 + lane] = d2 * inv * gi[64 + lane] + bi[64 + lane] + bh[64 + lane];
    __syncwarp();
    float c = 0.f, ov = 0.f;
    if (act) {
        float iv = gbuf[lane];
        ov = gbuf[40 + lane];
        float gv = gbuf[60 + lane];
        c = fast_sigmoid(iv) * fast_tanh(gv);
    }
    __syncwarp();
    float mu2 = warp_sum(c) * (1.f / 20.f);
    float dc = act ? (c - mu2) : 0.f;
    float var2 = warp_sum(dc * dc) * (1.f / 19.f);
    float inv2 = 1.f / (sqrtf(var2) + LN_EPS);
    float h = 0.f;
    if (act) {
        float cn = dc * inv2 * go[lane] + bo[lane];
        h = fast_sigmoid(ov) * fast_tanh(cn);
    }
    return h;
}

// ---------------- interpolation (half2 table in smem) -----------------------
__device__ __forceinline__ float interp_one_s(float xx,
                                              const unsigned int* __restrict__ tab) {
    float t = fmaf(xx, TAB_INV_STEP, TAB_T_OFF);
    t = fminf(fmaxf(t, 0.0f), TAB_T_MAX);        // clamp in t-space
    int i = __float2int_rd(t);
    float s = t - (float)i;
    unsigned int u = tab[i];                      // one LDS.32
    __half2 h = *reinterpret_cast<const __half2*>(&u);
    float2 q = __half22float2(h);                 // {F[i], F[i+1]}
    return fmaf(s, q.y - q.x, q.x);
}

// ---------------- the fused kernel ------------------------------------------
__global__ void __launch_bounds__(256)
fused_kernel(Weights w, const float4* __restrict__ x4, float4* __restrict__ o4,
             int n4, const float* __restrict__ x, float* __restrict__ out,
             int n) {
    __shared__ union SmemU {
        struct {
            float Wih0_s[WROWS * WPITCH];
            float Wih1_s[WROWS * WPITCH];
            float gates[8][GG];
            float hx[8][HH];
        } b;
        unsigned int tab[TAB_N];
    } smem;

    int tid = threadIdx.x, warp = tid >> 5, lane = tid & 31;
    const bool builder = blockIdx.x < NBUILD;

    if (builder) {
        // ---- build 8 table entries (one per warp), uncontended memory ----
        for (int idx = tid; idx < WROWS * WPITCH; idx += 256) {
            int r = idx / WPITCH, k = idx - r * WPITCH;
            float v0 = 0.f, v1 = 0.f;
            if (r < GG && k < HH) {
                v0 = w.Wih0[r * HH + k];
                v1 = w.Wih1[r * HH + k];
            }
            smem.b.Wih0_s[idx] = v0;
            smem.b.Wih1_s[idx] = v1;
        }
        __syncthreads();

        int entry = blockIdx.x * 8 + warp;
        float xe = fmaf((float)entry, TAB_STEP, TAB_XMIN);
        const bool act = lane < HH;

        // layer 1
        float hval = 0.f;
        if (act) hval = fmaf(xe, w.W1[lane], w.b1[lane]);
        {
            float mu = warp_sum(act ? hval : 0.f) * (1.f / 20.f);
            float d = act ? (hval - mu) : 0.f;
            float var = warp_sum(d * d) * (1.f / 19.f);
            float inv = 1.f / (sqrtf(var) + LN_EPS);
            if (act) hval = fast_tanh(d * inv * w.g1[lane] + w.be1[lane]);
        }

        float v[HH];
        if (act) smem.b.hx[warp][lane] = hval;
        __syncwarp();
#pragma unroll
        for (int k = 0; k < HH; k++) v[k] = smem.b.hx[warp][k];
        __syncwarp();

        hval = cell_warp(v, smem.b.Wih0_s, w.gi0, w.bi0, w.bh0, w.go0, w.bo0,
                         smem.b.gates[warp], lane);

        if (act) smem.b.hx[warp][lane] = hval;
        __syncwarp();
#pragma unroll
        for (int k = 0; k < HH; k++) v[k] = smem.b.hx[warp][k];
        __syncwarp();

        hval = cell_warp(v, smem.b.Wih1_s, w.gi1, w.bi1, w.bh1, w.go1, w.bo1,
                         smem.b.gates[warp], lane);

        float p = act ? hval * w.Wout[lane] : 0.f;
        p = warp_sum(p);
        if (lane == 0) {
            float val = p + w.bout[0];
            __half hv = __float2half_rn(val);
            __half* H = reinterpret_cast<__half*>(g_tab_h2);
            H[2 * entry] = hv;                       // pair[entry].x
            if (entry > 0) H[2 * entry - 1] = hv;    // pair[entry-1].y
            if (entry == TAB_N - 1) H[2 * entry + 1] = hv;  // defined
        }
        __syncthreads();
        if (tid == 0) {
            __threadfence();
            atomicAdd((int*)&g_count, 1);
        }
    }

    // ---- barrier: sleep-poll (no L2 storm) until all builders arrive ----
    if (tid == 0) {
        unsigned ns = 64;
        while (g_count < NBUILD) {
            __nanosleep(ns);
            if (ns < 1024) ns <<= 1;
        }
        __threadfence();
    }
    __syncthreads();

    // ---- stage 4KB half2 table into smem (one uint4 per thread) ----
    ((uint4*)smem.tab)[tid] = __ldcg(((const uint4*)g_tab_h2) + tid);
    __syncthreads();

    // ---- blocked interpolation (R8 shape): loads are L2-warm on replays ----
    int base = blockIdx.x * (256 * VPT) + tid;

    if (base + (VPT - 1) * 256 < n4) {           // hot: full block, no guards
        float4 xv[VPT];
#pragma unroll
        for (int j = 0; j < VPT; j++) xv[j] = x4[base + j * 256];
#pragma unroll
        for (int j = 0; j < VPT; j++) {
            float4 ov;
            ov.x = interp_one_s(xv[j].x, smem.tab);
            ov.y = interp_one_s(xv[j].y, smem.tab);
            ov.z = interp_one_s(xv[j].z, smem.tab);
            ov.w = interp_one_s(xv[j].w, smem.tab);
            __stcs(&o4[base + j * 256], ov);
        }
    } else {                                      // edge block
#pragma unroll
        for (int j = 0; j < VPT; j++) {
            int idx = base + j * 256;
            if (idx < n4) {
                float4 xv = x4[idx];
                float4 ov;
                ov.x = interp_one_s(xv.x, smem.tab);
                ov.y = interp_one_s(xv.y, smem.tab);
                ov.z = interp_one_s(xv.z, smem.tab);
                ov.w = interp_one_s(xv.w, smem.tab);
                __stcs(&o4[idx], ov);
            }
        }
        // n % 4 tail
        if (blockIdx.x == gridDim.x - 1 && tid < 32) {
            for (int i = n4 * 4 + tid; i < n; i += 32)
                out[i] = interp_one_s(x[i], smem.tab);
        }
    }

    // ---- exit: last block resets the barrier counters for the next replay --
    if (tid == 0) {
        int old = atomicAdd(&g_exit, 1);
        if (old == (int)gridDim.x - 1) {
            atomicExch((int*)&g_count, 0);
            atomicExch(&g_exit, 0);
        }
    }
}

extern "C" void kernel_launch(void* const* d_in, const int* in_sizes, int n_in,
                              void* d_out, int out_size) {
    Weights w;
    w.W1 = (const float*)d_in[1];
    w.b1 = (const float*)d_in[2];
    w.g1 = (const float*)d_in[3];
    w.be1 = (const float*)d_in[4];
    w.Wih0 = (const float*)d_in[5];
    w.gi0 = (const float*)d_in[7];
    w.bi0 = (const float*)d_in[8];
    w.bh0 = (const float*)d_in[10];
    w.go0 = (const float*)d_in[11];
    w.bo0 = (const float*)d_in[12];
    w.Wih1 = (const float*)d_in[13];
    w.gi1 = (const float*)d_in[15];
    w.bi1 = (const float*)d_in[16];
    w.bh1 = (const float*)d_in[18];
    w.go1 = (const float*)d_in[19];
    w.bo1 = (const float*)d_in[20];
    w.Wout = (const float*)d_in[21];
    w.bout = (const float*)d_in[22];

    const float* x = (const float*)d_in[0];
    float* out = (float*)d_out;
    int n = in_sizes[0];
    int n4 = n / 4;

    // blocked coverage like R8: one block covers 1024 float4s
    int blocks = (int)(((long long)n4 + 256LL * VPT - 1) / (256LL * VPT));
    if (blocks < NBUILD) blocks = NBUILD;

    fused_kernel<<<blocks, 256>>>(w, (const float4*)x, (float4*)out, n4,
                                  x, out, n);
}

// round 15
// speedup vs baseline: 1.2427x; 1.1307x over previous
#include <cuda_runtime.h>
#include <cuda_fp16.h>
#include <stdint.h>
#include <math.h>

// out[i] = F(x[i]) for a fixed smooth scalar F (weights shared across elems).
// Two kernels (fusion measured slower 3x — barrier costs > launch savings):
//   K1: warp-per-entry exact tabulation of F on [-6.5, 6.5], 1024 nodes,
//       stored as overlapping HALF2 pairs {F[j], F[j+1]} (4KB total).
//   K2: blocked VPT=4 linear interpolation, 128-thread blocks (13.2 CTA/SM),
//       table staged in smem, one LDS.32 gather per element.

#define HH 20
#define GG 80
#define LN_EPS 1e-5f

#define TAB_N 1024
#define TAB_XMIN (-6.5f)
#define TAB_XMAX (6.5f)
#define TAB_STEP ((TAB_XMAX - TAB_XMIN) / (float)(TAB_N - 1))
#define TAB_INV_STEP ((float)(TAB_N - 1) / (TAB_XMAX - TAB_XMIN))
#define TAB_T_OFF (-(TAB_XMIN) * TAB_INV_STEP)
#define TAB_T_MAX ((float)(TAB_N - 1) - 0.001f)

__device__ __half2 g_tab_h2[TAB_N];   // {F[j], F[j+1]}

struct Weights {
    const float *W1, *b1, *g1, *be1;
    const float *Wih0, *gi0, *bi0, *bh0, *go0, *bo0;
    const float *Wih1, *gi1, *bi1, *bh1, *go1, *bo1;
    const float *Wout, *bout;
};

__device__ __forceinline__ float fast_sigmoid(float z) {
    return 1.0f / (1.0f + __expf(-z));
}
__device__ __forceinline__ float fast_tanh(float z) {
    return 1.0f - 2.0f / (1.0f + __expf(2.0f * z));
}
__device__ __forceinline__ float warp_sum(float v) {
#pragma unroll
    for (int off = 16; off; off >>= 1) v += __shfl_xor_sync(0xffffffffu, v, off);
    return v;
}

// ===================== kernel 1: warp-per-entry table build =================
#define BUILD_WARPS 4
#define WPITCH 21
#define WROWS  96

__device__ __forceinline__ float cell_warp(const float* __restrict__ v,
                                           const float* __restrict__ Wsm,
                                           const float* gi, const float* bi,
                                           const float* bh, const float* go,
                                           const float* bo, float* gbuf,
                                           int lane) {
    const bool v2 = lane < 16;
    const bool act = lane < HH;
    const float* w0 = Wsm + lane * WPITCH;
    const float* w1 = Wsm + (32 + lane) * WPITCH;
    const float* w2 = Wsm + (64 + lane) * WPITCH;  // rows >= 80 are zero
    float a0 = 0.f, a1 = 0.f, a2 = 0.f;
#pragma unroll
    for (int k = 0; k < HH; k++) {
        a0 = fmaf(v[k], w0[k], a0);
        a1 = fmaf(v[k], w1[k], a1);
        a2 = fmaf(v[k], w2[k], a2);
    }
    float mu = warp_sum(a0 + a1 + a2) * (1.f / 80.f);
    float d0 = a0 - mu, d1 = a1 - mu, d2 = v2 ? (a2 - mu) : 0.f;
    float var = warp_sum(fmaf(d0, d0, fmaf(d1, d1, d2 * d2))) * (1.f / 79.f);
    float inv = 1.f / (sqrtf(var) + LN_EPS);
    gbuf[lane]      = d0 * inv * gi[lane]      + bi[lane]      + bh[lane];
    gbuf[32 + lane] = d1 * inv * gi[32 + lane] + bi[32 + lane] + bh[32 + lane];
    if (v2)
        gbuf[64 + lane] = d2 * inv * gi[64 + lane] + bi[64 + lane] + bh[64 + lane];
    __syncwarp();
    float c = 0.f, ov = 0.f;
    if (act) {
        float iv = gbuf[lane];
        ov = gbuf[40 + lane];
        float gv = gbuf[60 + lane];
        c = fast_sigmoid(iv) * fast_tanh(gv);
    }
    __syncwarp();
    float mu2 = warp_sum(c) * (1.f / 20.f);
    float dc = act ? (c - mu2) : 0.f;
    float var2 = warp_sum(dc * dc) * (1.f / 19.f);
    float inv2 = 1.f / (sqrtf(var2) + LN_EPS);
    float h = 0.f;
    if (act) {
        float cn = dc * inv2 * go[lane] + bo[lane];
        h = fast_sigmoid(ov) * fast_tanh(cn);
    }
    return h;
}

__global__ void __launch_bounds__(32 * BUILD_WARPS)
build_table_kernel(Weights w) {
    __shared__ float Wih0_s[WROWS * WPITCH];
    __shared__ float Wih1_s[WROWS * WPITCH];
    __shared__ float gates_s[BUILD_WARPS][GG];
    __shared__ float hx_s[BUILD_WARPS][HH];

    int tid = threadIdx.x;
    for (int idx = tid; idx < WROWS * WPITCH; idx += blockDim.x) {
        int r = idx / WPITCH, k = idx - r * WPITCH;
        float v0 = 0.f, v1 = 0.f;
        if (r < GG && k < HH) { v0 = w.Wih0[r * HH + k]; v1 = w.Wih1[r * HH + k]; }
        Wih0_s[idx] = v0;
        Wih1_s[idx] = v1;
    }
    __syncthreads();

    int warp = tid >> 5, lane = tid & 31;
    int entry = blockIdx.x * BUILD_WARPS + warp;
    float x = fmaf((float)entry, TAB_STEP, TAB_XMIN);
    const bool act = lane < HH;

    // layer 1
    float hval = 0.f;
    if (act) hval = fmaf(x, w.W1[lane], w.b1[lane]);
    {
        float mu = warp_sum(act ? hval : 0.f) * (1.f / 20.f);
        float d = act ? (hval - mu) : 0.f;
        float var = warp_sum(d * d) * (1.f / 19.f);
        float inv = 1.f / (sqrtf(var) + LN_EPS);
        if (act) hval = fast_tanh(d * inv * w.g1[lane] + w.be1[lane]);
    }

    float v[HH];
    if (act) hx_s[warp][lane] = hval;
    __syncwarp();
#pragma unroll
    for (int k = 0; k < HH; k++) v[k] = hx_s[warp][k];
    __syncwarp();

    hval = cell_warp(v, Wih0_s, w.gi0, w.bi0, w.bh0, w.go0, w.bo0,
                     gates_s[warp], lane);

    if (act) hx_s[warp][lane] = hval;
    __syncwarp();
#pragma unroll
    for (int k = 0; k < HH; k++) v[k] = hx_s[warp][k];
    __syncwarp();

    hval = cell_warp(v, Wih1_s, w.gi1, w.bi1, w.bh1, w.go1, w.bo1,
                     gates_s[warp], lane);

    float p = act ? hval * w.Wout[lane] : 0.f;
    p = warp_sum(p);
    if (lane == 0) {
        float val = p + w.bout[0];
        __half hv = __float2half_rn(val);
        __half* H = reinterpret_cast<__half*>(g_tab_h2);
        H[2 * entry] = hv;                       // pair[entry].x
        if (entry > 0) H[2 * entry - 1] = hv;    // pair[entry-1].y
        if (entry == TAB_N - 1) H[2 * entry + 1] = hv;  // defined, never read
    }
}

// ===================== kernel 2: smem half2-table linear interp =============
__device__ __forceinline__ float interp_one_s(float xx,
                                              const unsigned int* __restrict__ tab) {
    float t = fmaf(xx, TAB_INV_STEP, TAB_T_OFF);
    t = fminf(fmaxf(t, 0.0f), TAB_T_MAX);        // clamp in t-space
    int i = __float2int_rd(t);
    float s = t - (float)i;
    unsigned int u = tab[i];                      // one LDS.32 (random banks)
    __half2 h = *reinterpret_cast<const __half2*>(&u);
    float2 q = __half22float2(h);                 // {F[i], F[i+1]}
    return fmaf(s, q.y - q.x, q.x);
}

#define ITHREADS 128   // small blocks -> 13.2 CTAs/SM, occ ~82%
#define VPT 4          // float4s per thread, blocked addressing

__global__ void __launch_bounds__(ITHREADS)
interp_kernel(const float4* __restrict__ x4, float4* __restrict__ o4, int n4,
              const float* __restrict__ x, float* __restrict__ out, int n) {
    __shared__ unsigned int tab_s[TAB_N];

    // stage the 4KB table: 2 uint4 loads per thread, coalesced
    {
        const uint4* src = (const uint4*)g_tab_h2;
        uint4* dst = (uint4*)tab_s;
#pragma unroll
        for (int j = 0; j < TAB_N / 4 / ITHREADS; j++)
            dst[threadIdx.x + j * ITHREADS] = src[threadIdx.x + j * ITHREADS];
    }
    __syncthreads();

    int base = blockIdx.x * (ITHREADS * VPT) + threadIdx.x;

    if (base + (VPT - 1) * ITHREADS < n4) {      // hot: full block, no guards
        float4 xv[VPT];
#pragma unroll
        for (int j = 0; j < VPT; j++) xv[j] = __ldcs(&x4[base + j * ITHREADS]);
#pragma unroll
        for (int j = 0; j < VPT; j++) {
            float4 ov;
            ov.x = interp_one_s(xv[j].x, tab_s);
            ov.y = interp_one_s(xv[j].y, tab_s);
            ov.z = interp_one_s(xv[j].z, tab_s);
            ov.w = interp_one_s(xv[j].w, tab_s);
            __stcs(&o4[base + j * ITHREADS], ov);
        }
    } else {                                      // edge block
#pragma unroll
        for (int j = 0; j < VPT; j++) {
            int idx = base + j * ITHREADS;
            if (idx < n4) {
                float4 xv = __ldcs(&x4[idx]);
                float4 ov;
                ov.x = interp_one_s(xv.x, tab_s);
                ov.y = interp_one_s(xv.y, tab_s);
                ov.z = interp_one_s(xv.z, tab_s);
                ov.w = interp_one_s(xv.w, tab_s);
                __stcs(&o4[idx], ov);
            }
        }
        // n % 4 tail
        if (blockIdx.x == gridDim.x - 1 && threadIdx.x < 32) {
            for (int i = n4 * 4 + threadIdx.x; i < n; i += 32)
                out[i] = interp_one_s(x[i], tab_s);
        }
    }
}

extern "C" void kernel_launch(void* const* d_in, const int* in_sizes, int n_in,
                              void* d_out, int out_size) {
    Weights w;
    w.W1 = (const float*)d_in[1];
    w.b1 = (const float*)d_in[2];
    w.g1 = (const float*)d_in[3];
    w.be1 = (const float*)d_in[4];
    w.Wih0 = (const float*)d_in[5];
    w.gi0 = (const float*)d_in[7];
    w.bi0 = (const float*)d_in[8];
    w.bh0 = (const float*)d_in[10];
    w.go0 = (const float*)d_in[11];
    w.bo0 = (const float*)d_in[12];
    w.Wih1 = (const float*)d_in[13];
    w.gi1 = (const float*)d_in[15];
    w.bi1 = (const float*)d_in[16];
    w.bh1 = (const float*)d_in[18];
    w.go1 = (const float*)d_in[19];
    w.bo1 = (const float*)d_in[20];
    w.Wout = (const float*)d_in[21];
    w.bout = (const float*)d_in[22];

    const float* x = (const float*)d_in[0];
    float* out = (float*)d_out;
    int n = in_sizes[0];
    int n4 = n / 4;

    build_table_kernel<<<TAB_N / BUILD_WARPS, 32 * BUILD_WARPS>>>(w);

    int per_block = ITHREADS * VPT;
    int blocks = (n4 + per_block - 1) / per_block;
    if (blocks == 0) blocks = 1;
    interp_kernel<<<blocks, ITHREADS>>>((const float4*)x, (float4*)out, n4,
                                        x, out, n);
}

// round 16
// speedup vs baseline: 1.2909x; 1.0388x over previous
#include <cuda_runtime.h>
#include <cuda_fp16.h>
#include <stdint.h>
#include <math.h>

// out[i] = F(x[i]) for a fixed smooth scalar F (weights shared across elems).
// Two kernels:
//   K1: warp-per-entry exact tabulation of F on [-6.5, 6.5], 1024 nodes,
//       half2 pairs {F[j], F[j+1]}; 128 blocks x 8 warps = ONE wave on 148 SMs.
//   K2: blocked VPT=4 linear interpolation, 128-thread blocks, smem table,
//       one LDS.32 gather per element, FFMA.SAT-based clamp.

#define HH 20
#define GG 80
#define LN_EPS 1e-5f

#define TAB_N 1024
#define TAB_XMIN (-6.5f)
#define TAB_XMAX (6.5f)
#define TAB_STEP ((TAB_XMAX - TAB_XMIN) / (float)(TAB_N - 1))
#define TAB_INV_STEP ((float)(TAB_N - 1) / (TAB_XMAX - TAB_XMIN))
#define TAB_T_OFF (-(TAB_XMIN) * TAB_INV_STEP)
#define TAB_T_MAX ((float)(TAB_N - 1) - 0.001f)
// normalized clamp: t = saturate(x*TAB_A + TAB_B) * TAB_T_MAX
#define TAB_A (TAB_INV_STEP / TAB_T_MAX)
#define TAB_B (TAB_T_OFF / TAB_T_MAX)

__device__ __half2 g_tab_h2[TAB_N];   // {F[j], F[j+1]}

struct Weights {
    const float *W1, *b1, *g1, *be1;
    const float *Wih0, *gi0, *bi0, *bh0, *go0, *bo0;
    const float *Wih1, *gi1, *bi1, *bh1, *go1, *bo1;
    const float *Wout, *bout;
};

__device__ __forceinline__ float fast_sigmoid(float z) {
    return 1.0f / (1.0f + __expf(-z));
}
__device__ __forceinline__ float fast_tanh(float z) {
    return 1.0f - 2.0f / (1.0f + __expf(2.0f * z));
}
__device__ __forceinline__ float warp_sum(float v) {
#pragma unroll
    for (int off = 16; off; off >>= 1) v += __shfl_xor_sync(0xffffffffu, v, off);
    return v;
}

// ===================== kernel 1: warp-per-entry table build =================
#define BUILD_WARPS 8          // 1024/8 = 128 blocks = one wave on 148 SMs
#define WPITCH 21
#define WROWS  96

__device__ __forceinline__ float cell_warp(const float* __restrict__ v,
                                           const float* __restrict__ Wsm,
                                           const float* gi, const float* bi,
                                           const float* bh, const float* go,
                                           const float* bo, float* gbuf,
                                           int lane) {
    const bool v2 = lane < 16;
    const bool act = lane < HH;
    const float* w0 = Wsm + lane * WPITCH;
    const float* w1 = Wsm + (32 + lane) * WPITCH;
    const float* w2 = Wsm + (64 + lane) * WPITCH;  // rows >= 80 are zero
    float a0 = 0.f, a1 = 0.f, a2 = 0.f;
#pragma unroll
    for (int k = 0; k < HH; k++) {
        a0 = fmaf(v[k], w0[k], a0);
        a1 = fmaf(v[k], w1[k], a1);
        a2 = fmaf(v[k], w2[k], a2);
    }
    float mu = warp_sum(a0 + a1 + a2) * (1.f / 80.f);
    float d0 = a0 - mu, d1 = a1 - mu, d2 = v2 ? (a2 - mu) : 0.f;
    float var = warp_sum(fmaf(d0, d0, fmaf(d1, d1, d2 * d2))) * (1.f / 79.f);
    float inv = 1.f / (sqrtf(var) + LN_EPS);
    gbuf[lane]      = d0 * inv * gi[lane]      + bi[lane]      + bh[lane];
    gbuf[32 + lane] = d1 * inv * gi[32 + lane] + bi[32 + lane] + bh[32 + lane];
    if (v2)
        gbuf[64 + lane] = d2 * inv * gi[64 + lane] + bi[64 + lane] + bh[64 + lane];
    __syncwarp();
    float c = 0.f, ov = 0.f;
    if (act) {
        float iv = gbuf[lane];
        ov = gbuf[40 + lane];
        float gv = gbuf[60 + lane];
        c = fast_sigmoid(iv) * fast_tanh(gv);
    }
    __syncwarp();
    float mu2 = warp_sum(c) * (1.f / 20.f);
    float dc = act ? (c - mu2) : 0.f;
    float var2 = warp_sum(dc * dc) * (1.f / 19.f);
    float inv2 = 1.f / (sqrtf(var2) + LN_EPS);
    float h = 0.f;
    if (act) {
        float cn = dc * inv2 * go[lane] + bo[lane];
        h = fast_sigmoid(ov) * fast_tanh(cn);
    }
    return h;
}

__global__ void __launch_bounds__(32 * BUILD_WARPS)
build_table_kernel(Weights w) {
    __shared__ float Wih0_s[WROWS * WPITCH];
    __shared__ float Wih1_s[WROWS * WPITCH];
    __shared__ float gates_s[BUILD_WARPS][GG];
    __shared__ float hx_s[BUILD_WARPS][HH];

    int tid = threadIdx.x;
    for (int idx = tid; idx < WROWS * WPITCH; idx += blockDim.x) {
        int r = idx / WPITCH, k = idx - r * WPITCH;
        float v0 = 0.f, v1 = 0.f;
        if (r < GG && k < HH) { v0 = w.Wih0[r * HH + k]; v1 = w.Wih1[r * HH + k]; }
        Wih0_s[idx] = v0;
        Wih1_s[idx] = v1;
    }
    __syncthreads();

    int warp = tid >> 5, lane = tid & 31;
    int entry = blockIdx.x * BUILD_WARPS + warp;
    float x = fmaf((float)entry, TAB_STEP, TAB_XMIN);
    const bool act = lane < HH;

    // layer 1
    float hval = 0.f;
    if (act) hval = fmaf(x, w.W1[lane], w.b1[lane]);
    {
        float mu = warp_sum(act ? hval : 0.f) * (1.f / 20.f);
        float d = act ? (hval - mu) : 0.f;
        float var = warp_sum(d * d) * (1.f / 19.f);
        float inv = 1.f / (sqrtf(var) + LN_EPS);
        if (act) hval = fast_tanh(d * inv * w.g1[lane] + w.be1[lane]);
    }

    float v[HH];
    if (act) hx_s[warp][lane] = hval;
    __syncwarp();
#pragma unroll
    for (int k = 0; k < HH; k++) v[k] = hx_s[warp][k];
    __syncwarp();

    hval = cell_warp(v, Wih0_s, w.gi0, w.bi0, w.bh0, w.go0, w.bo0,
                     gates_s[warp], lane);

    if (act) hx_s[warp][lane] = hval;
    __syncwarp();
#pragma unroll
    for (int k = 0; k < HH; k++) v[k] = hx_s[warp][k];
    __syncwarp();

    hval = cell_warp(v, Wih1_s, w.gi1, w.bi1, w.bh1, w.go1, w.bo1,
                     gates_s[warp], lane);

    float p = act ? hval * w.Wout[lane] : 0.f;
    p = warp_sum(p);
    if (lane == 0) {
        float val = p + w.bout[0];
        __half hv = __float2half_rn(val);
        __half* H = reinterpret_cast<__half*>(g_tab_h2);
        H[2 * entry] = hv;                       // pair[entry].x
        if (entry > 0) H[2 * entry - 1] = hv;    // pair[entry-1].y
        if (entry == TAB_N - 1) H[2 * entry + 1] = hv;  // defined, never read
    }
}

// ===================== kernel 2: smem half2-table linear interp =============
__device__ __forceinline__ float interp_one_s(float xx,
                                              const unsigned int* __restrict__ tab) {
    float t = __saturatef(fmaf(xx, TAB_A, TAB_B)) * TAB_T_MAX;  // FFMA.SAT+FMUL
    int i = __float2int_rd(t);
    float s = t - (float)i;
    unsigned int u = tab[i];                      // one LDS.32 (random banks)
    __half2 h = *reinterpret_cast<const __half2*>(&u);
    float2 q = __half22float2(h);                 // {F[i], F[i+1]}
    return fmaf(s, q.y - q.x, q.x);
}

#define ITHREADS 128   // 1954 blocks -> ~13 CTAs/SM
#define VPT 4          // float4s per thread, blocked addressing

__global__ void __launch_bounds__(ITHREADS)
interp_kernel(const float4* __restrict__ x4, float4* __restrict__ o4, int n4,
              const float* __restrict__ x, float* __restrict__ out, int n) {
    __shared__ unsigned int tab_s[TAB_N];

    // stage the 4KB table: 2 uint4 loads per thread, coalesced
    {
        const uint4* src = (const uint4*)g_tab_h2;
        uint4* dst = (uint4*)tab_s;
#pragma unroll
        for (int j = 0; j < TAB_N / 4 / ITHREADS; j++)
            dst[threadIdx.x + j * ITHREADS] = src[threadIdx.x + j * ITHREADS];
    }
    __syncthreads();

    int base = blockIdx.x * (ITHREADS * VPT) + threadIdx.x;

    if (base + (VPT - 1) * ITHREADS < n4) {      // hot: full block, no guards
        float4 xv[VPT];
#pragma unroll
        for (int j = 0; j < VPT; j++) xv[j] = __ldcs(&x4[base + j * ITHREADS]);
#pragma unroll
        for (int j = 0; j < VPT; j++) {
            float4 ov;
            ov.x = interp_one_s(xv[j].x, tab_s);
            ov.y = interp_one_s(xv[j].y, tab_s);
            ov.z = interp_one_s(xv[j].z, tab_s);
            ov.w = interp_one_s(xv[j].w, tab_s);
            __stcs(&o4[base + j * ITHREADS], ov);
        }
    } else {                                      // edge block
#pragma unroll
        for (int j = 0; j < VPT; j++) {
            int idx = base + j * ITHREADS;
            if (idx < n4) {
                float4 xv = __ldcs(&x4[idx]);
                float4 ov;
                ov.x = interp_one_s(xv.x, tab_s);
                ov.y = interp_one_s(xv.y, tab_s);
                ov.z = interp_one_s(xv.z, tab_s);
                ov.w = interp_one_s(xv.w, tab_s);
                __stcs(&o4[idx], ov);
            }
        }
        // n % 4 tail
        if (blockIdx.x == gridDim.x - 1 && threadIdx.x < 32) {
            for (int i = n4 * 4 + threadIdx.x; i < n; i += 32)
                out[i] = interp_one_s(x[i], tab_s);
        }
    }
}

extern "C" void kernel_launch(void* const* d_in, const int* in_sizes, int n_in,
                              void* d_out, int out_size) {
    Weights w;
    w.W1 = (const float*)d_in[1];
    w.b1 = (const float*)d_in[2];
    w.g1 = (const float*)d_in[3];
    w.be1 = (const float*)d_in[4];
    w.Wih0 = (const float*)d_in[5];
    w.gi0 = (const float*)d_in[7];
    w.bi0 = (const float*)d_in[8];
    w.bh0 = (const float*)d_in[10];
    w.go0 = (const float*)d_in[11];
    w.bo0 = (const float*)d_in[12];
    w.Wih1 = (const float*)d_in[13];
    w.gi1 = (const float*)d_in[15];
    w.bi1 = (const float*)d_in[16];
    w.bh1 = (const float*)d_in[18];
    w.go1 = (const float*)d_in[19];
    w.bo1 = (const float*)d_in[20];
    w.Wout = (const float*)d_in[21];
    w.bout = (const float*)d_in[22];

    const float* x = (const float*)d_in[0];
    float* out = (float*)d_out;
    int n = in_sizes[0];
    int n4 = n / 4;

    build_table_kernel<<<TAB_N / BUILD_WARPS, 32 * BUILD_WARPS>>>(w);

    int per_block = ITHREADS * VPT;
    int blocks = (n4 + per_block - 1) / per_block;
    if (blocks == 0) blocks = 1;
    interp_kernel<<<blocks, ITHREADS>>>((const float4*)x, (float4*)out, n4,
                                        x, out, n);
}